// round 11
// baseline (speedup 1.0000x reference)
#include <cuda_runtime.h>
#include <cstdint>
#include <cstddef>

// out[b] = weight[b] + top1000_scatter_mask(|difference[b]|), B=64, N=1M/batch.
// R11 (= R10 + compile fix): single fused kernel. Streaming copy + candidate
// gather + free histogram; the last-finishing block of each batch (done-ticket
// pattern) runs selection + scatter while other SMs still stream.

namespace {

constexpr int B      = 64;
constexpr int NPB    = 1 << 20;
constexpr int TOPN   = 1000;
constexpr unsigned CUT = 0x404CCCCDu; // float bits of 3.2f (rank-1000 ~3.29 sigma)
constexpr int BPB    = 1024;          // blocks per batch
constexpr int DCAP   = 16384;         // dense candidate capacity (mean ~1374)
constexpr int NBIN   = 4096;          // fine bins: (key - CUT) >> 12, clamped
constexpr int BCAP   = 1024;          // boundary list capacity (reuses s_key/s_idx)

__device__ unsigned g_dkey[B][DCAP];
__device__ unsigned g_didx[B][DCAP];
__device__ unsigned g_dcnt[B * 32];   // 128B-padded; reset by selection block
__device__ unsigned g_done[B * 32];   // completion tickets; reset by selection block
__device__ unsigned g_hist[B][NBIN];  // built by all blocks; zeroed by selection block

__device__ __forceinline__ unsigned keybin(unsigned key) {
    unsigned d = key - CUT;           // key >= CUT on candidate path
    unsigned bi = d >> 12;
    return bi < (unsigned)NBIN ? bi : (unsigned)(NBIN - 1);
}

__global__ void __launch_bounds__(256, 8)
k_fused(const float4* __restrict__ diff, const float4* __restrict__ w,
        float4* __restrict__ out, const int* __restrict__ ep) {
    __shared__ unsigned s_key[1024];
    __shared__ unsigned s_idx[1024];
    __shared__ unsigned s_hist[NBIN];          // selection-phase only
    __shared__ unsigned s_wsum[8], s_wsuf[8];
    __shared__ unsigned s_n, s_base, s_rank;
    __shared__ unsigned s_p0, s_rem, s_m, s_bn;
    __shared__ unsigned s_prefix, s_rem2, s_tcnt;

    unsigned tid = threadIdx.x;
    if (tid == 0) s_n = 0u;
    __syncthreads();

    // ---------------- Streaming phase (every block) ----------------
    unsigned b    = blockIdx.x & 63u;          // interleaved batch mapping
    unsigned bblk = blockIdx.x >> 6;
    unsigned t    = (b << 18) + bblk * 256u + tid;
    float4 d = __ldcs(&diff[t]);
    __stcs(&out[t], __ldcs(&w[t]));

    unsigned e0 = (bblk * 256u + tid) << 2;

    unsigned keys[4] = {__float_as_uint(d.x) & 0x7FFFFFFFu,
                        __float_as_uint(d.y) & 0x7FFFFFFFu,
                        __float_as_uint(d.z) & 0x7FFFFFFFu,
                        __float_as_uint(d.w) & 0x7FFFFFFFu};
#pragma unroll
    for (int j = 0; j < 4; ++j) {
        if (keys[j] >= CUT) {                  // ~0.137% of elements
            unsigned p = atomicAdd(&s_n, 1u);
            s_key[p] = keys[j];
            s_idx[p] = e0 + j;
        }
    }
    __syncthreads();

    unsigned n = s_n;
    if (n) {
        if (tid == 0)
            s_base = atomicAdd(&g_dcnt[b * 32], n);
        __syncthreads();
        unsigned base = s_base;
        for (unsigned i = tid; i < n; i += 256u) {
            unsigned k = s_key[i];
            unsigned slot = base + i;
            if (slot < (unsigned)DCAP) {
                g_dkey[b][slot] = k;
                g_didx[b][slot] = s_idx[i];
            }
            atomicAdd(&g_hist[b][keybin(k)], 1u);   // ~1.4/block, spread: hidden
        }
    }

    // ---------------- Completion ticket ----------------
    __threadfence();
    if (tid == 0) s_rank = atomicAdd(&g_done[b * 32], 1u);
    __syncthreads();
    if (s_rank != (unsigned)(BPB - 1)) return;

    // ============ Selection (last block of batch b only) ============
    float* outf = (float*)out;                 // scalar view for scatter
    const float* diffs = (const float*)diff;
    unsigned lane = tid & 31u, wrp = tid >> 5;
    int epoch = ep[0];
    bool hot = (epoch > 1000) && (epoch < 18000) && (epoch % 200 == 0);

    unsigned raw = g_dcnt[b * 32];
    bool fast = (raw >= (unsigned)TOPN) && (raw <= (unsigned)DCAP);
    size_t gbase = (size_t)b * (size_t)NPB;
    unsigned dom = fast ? raw : (unsigned)NPB;

    bool done_sel = !hot;

    if (hot && fast) {
        // ---- Load histogram to smem (L2-warm), compute chunk sums ----
        unsigned P = 0;
#pragma unroll
        for (int q = 0; q < 4; ++q) {
            uint4 v = ((const uint4*)&g_hist[b][0])[tid * 4u + q];
            ((uint4*)s_hist)[tid * 4u + q] = v;
            P += v.x + v.y + v.z + v.w;
        }
        if (tid == 0) s_bn = 0u;

        // ---- 2-level inclusive suffix scan (256 chunks of 16 bins) ----
        unsigned s = P;
#pragma unroll
        for (unsigned off = 1; off < 32; off <<= 1) {
            unsigned v = __shfl_down_sync(0xFFFFFFFFu, s, off);
            if (lane + off < 32u) s += v;
        }
        if (lane == 0) s_wsum[wrp] = s;
        __syncthreads();
        if (tid == 0) {
            unsigned acc = 0;
            for (int wi = 7; wi >= 0; --wi) { s_wsuf[wi] = acc; acc += s_wsum[wi]; }
        }
        __syncthreads();
        unsigned above = (s + s_wsuf[wrp]) - P;   // keys strictly above my chunk
        unsigned acc = above;
#pragma unroll
        for (int q = 15; q >= 0; --q) {
            unsigned bin = tid * 16u + (unsigned)q;
            unsigned hq  = s_hist[bin];
            if (acc < (unsigned)TOPN && acc + hq >= (unsigned)TOPN) {
                s_p0 = bin; s_rem = (unsigned)TOPN - acc; s_m = hq;
            }
            acc += hq;
        }
        __syncthreads();

        unsigned p0 = s_p0, rem = s_rem, m = s_m;

        if (m <= (unsigned)BCAP) {
            // ---- Single pass: scatter winners, collect boundary bin ----
            // (s_key/s_idx reused as the boundary list.)
            for (unsigned i = tid; i < dom; i += 256u) {
                unsigned k  = g_dkey[b][i];
                unsigned bi = keybin(k);
                if (bi > p0) {
                    outf[gbase + g_didx[b][i]] += 1.0f;
                } else if (bi == p0) {
                    unsigned p = atomicAdd(&s_bn, 1u);
                    s_key[p] = k;                    // p < m <= BCAP
                    s_idx[p] = g_didx[b][i];
                }
            }
            __syncthreads();
            // ---- Exact boundary ranking (key desc, idx asc) ----
            for (unsigned u = tid; u < m; u += 256u) {
                unsigned mk = s_key[u], mi = s_idx[u];
                unsigned rank = 0u;
                for (unsigned j = 0; j < m; ++j) {
                    unsigned kj = s_key[j];
                    rank += (kj > mk || (kj == mk && s_idx[j] < mi)) ? 1u : 0u;
                }
                if (rank < rem) outf[gbase + mi] += 1.0f;
            }
            done_sel = true;
        }
        __syncthreads();
    }

    if (!done_sel) {
        // ==== Fallback: exact 4-round radix select (unreachable on bench) ====
        if (tid == 0) { s_prefix = 0u; s_rem2 = (unsigned)TOPN; s_tcnt = 0u; }
        __syncthreads();

        auto getkey = [&](unsigned i) -> unsigned {
            if (fast) return g_dkey[b][i];
            return __float_as_uint(diffs[gbase + i]) & 0x7FFFFFFFu;
        };
        auto getidx = [&](unsigned i) -> unsigned {
            if (fast) return g_didx[b][i];
            return i;
        };

        const int      SH[4] = {23, 15, 7, 0};
        const unsigned BM[4] = {255u, 255u, 255u, 127u};
#pragma unroll 1
        for (int r = 0; r < 4; ++r) {
            if (tid < 256u) s_hist[tid] = 0u;
            __syncthreads();
            int      sh     = SH[r];
            int      hish   = sh + (r == 3 ? 7 : 8);
            unsigned prefix = s_prefix;
            for (unsigned i = tid; i < dom; i += 256u) {
                unsigned key = getkey(i);
                if (((key ^ prefix) >> hish) == 0u)
                    atomicAdd(&s_hist[(key >> sh) & BM[r]], 1u);
            }
            __syncthreads();
            if (tid == 0) {
                unsigned need = s_rem2, a2 = 0u;
                int bin = (int)BM[r];
                for (; bin > 0; --bin) {
                    unsigned c = s_hist[bin];
                    if (a2 + c >= need) break;
                    a2 += c;
                }
                s_rem2   = need - a2;
                s_prefix = prefix | ((unsigned)bin << sh);
            }
            __syncthreads();
        }

        unsigned thr = s_prefix, req = s_rem2;

        for (unsigned i = tid; i < dom; i += 256u) {
            unsigned key = getkey(i);
            if (key > thr) {
                outf[gbase + getidx(i)] += 1.0f;
            } else if (key == thr) {
                unsigned p = atomicAdd(&s_tcnt, 1u);
                if (p < (unsigned)BCAP) s_key[p] = getidx(i);
            }
        }
        __syncthreads();

        unsigned tc = s_tcnt;
        if (tc <= (unsigned)BCAP) {
            for (unsigned u = tid; u < tc; u += 256u) {
                unsigned my = s_key[u], rank = 0u;
                for (unsigned j = 0; j < tc; ++j) rank += (s_key[j] < my) ? 1u : 0u;
                if (rank < req) outf[gbase + my] += 1.0f;
            }
        } else {
            for (unsigned i = tid; i < dom; i += 256u) {
                unsigned key = getkey(i);
                if (key != thr) continue;
                unsigned idx = getidx(i), rank = 0u;
                for (unsigned j = 0; j < dom; ++j) {
                    if (getkey(j) == thr && getidx(j) < idx) ++rank;
                }
                if (rank < req) outf[gbase + idx] += 1.0f;
            }
        }
        __syncthreads();
    }

    // ---- Epilogue: reset per-batch state for the next graph replay ----
    for (unsigned i = tid; i < (unsigned)NBIN; i += 256u) g_hist[b][i] = 0u;
    if (tid == 0) { g_dcnt[b * 32] = 0u; g_done[b * 32] = 0u; }
}

} // namespace

extern "C" void kernel_launch(void* const* d_in, const int* in_sizes, int n_in,
                              void* d_out, int out_size) {
    const float* diff = (const float*)d_in[0];
    const float* w    = (const float*)d_in[1];
    const int*   ep   = (const int*)d_in[2];
    float*       out  = (float*)d_out;

    k_fused<<<B * BPB, 256>>>((const float4*)diff, (const float4*)w,
                              (float4*)out, ep);
}